// round 16
// baseline (speedup 1.0000x reference)
#include <cuda_runtime.h>

#define LW 512
#define LH 512
#define NIMG 12
#define RAD 8
#define HW 2048

// Low-res {A, b} interleaved — only intermediate that touches HBM (~25 MB).
__device__ float2 g_AB[(size_t)NIMG * LH * LW];

// ---------------------------------------------------------------------------
// Kernel 1 (fused stats) — R12 version VERBATIM (passed, ~27us plateau).
// ---------------------------------------------------------------------------
#define TC 64                 // out cols per tile
#define TR 16                 // out rows per tile
#define VC (TC + 2 * RAD)     // 80 loaded cols
#define VW 89                 // padded V row width (vpad(79)=88 -> 89)
#define STH 160
#define HTR 8                 // rows per chain group

__device__ __forceinline__ int vpad(int v) { return v + (v >> 3); }

__global__ __launch_bounds__(STH) void stats_kernel(const float* __restrict__ lrx,
                                                    const float* __restrict__ lry) {
    __shared__ float4 Vsh[TR][VW];              // 22.8 KB vertical window sums

    int img = blockIdx.z;
    int cb  = blockIdx.x * TC;
    int r0  = blockIdx.y * TR;
    int t   = threadIdx.x;

    const float* xim = lrx + (size_t)img * LH * LW;
    const float* yim = lry + (size_t)img * LH * LW;

    // ---------------- phase 1: two parallel vertical chain groups ---------
    {
        int grp = (t >= VC) ? 1 : 0;            // 0: rows 0-7, 1: rows 8-15
        int tt  = t - grp * VC;                 // 0..79 within group
        int gcol = cb - RAD + tt;               // may be <0 or >=LW at edges
        bool cok = (gcol >= 0 && gcol < LW);
        int rbase = r0 + grp * HTR;             // first output row of group

        float sx = 0.f, sy = 0.f, sxy = 0.f, sxx = 0.f;

#pragma unroll
        for (int j = 0; j < 2 * RAD + 1; ++j) {
            int rr = rbase - RAD + j;
            float xv = 0.f, yv = 0.f;
            if (cok && rr >= 0 && rr < LH) {
                xv = __ldg(xim + (size_t)rr * LW + gcol);
                yv = __ldg(yim + (size_t)rr * LW + gcol);
            }
            sx += xv; sy += yv; sxy += xv * yv; sxx += xv * xv;
        }

#pragma unroll 4
        for (int i = 0; i < HTR; ++i) {
            Vsh[grp * HTR + i][vpad(tt)] = make_float4(sx, sy, sxy, sxx);

            int rsub = rbase + i - RAD;         // row leaving (max 503 < LH)
            int radd = rbase + i + RAD + 1;     // row entering
            float ox = 0.f, oy = 0.f;
            if (cok && rsub >= 0) {
                ox = __ldg(xim + (size_t)rsub * LW + gcol);
                oy = __ldg(yim + (size_t)rsub * LW + gcol);
            }
            float xv = 0.f, yv = 0.f;
            if (cok && radd < LH) {
                xv = __ldg(xim + (size_t)radd * LW + gcol);
                yv = __ldg(yim + (size_t)radd * LW + gcol);
            }
            sx  += xv - ox;
            sy  += yv - oy;
            sxy += xv * yv - ox * oy;
            sxx += xv * xv - ox * ox;
        }
    }
    __syncthreads();

    // ---------------- phase 2: horizontal sliding + A,b (direct write) ----
    if (t < 128) {
        int i   = t >> 3;          // row in tile, 0..15
        int seg = t & 7;           // 8-px segment, 0..7
        int c0  = seg * 8;
        int r   = r0 + i;

        int ylo = r - RAD; if (ylo < 0) ylo = 0;
        int yhi = r + RAD; if (yhi > LH - 1) yhi = LH - 1;
        float ny = (float)(yhi - ylo + 1);

        float sx = 0.f, sy = 0.f, sxy = 0.f, sxx = 0.f;
#pragma unroll
        for (int v = c0; v <= c0 + 2 * RAD; ++v) {
            float4 w = Vsh[i][vpad(v)];
            sx += w.x; sy += w.y; sxy += w.z; sxx += w.w;
        }

        size_t abase = (size_t)img * LH * LW + (size_t)r * LW;
#pragma unroll
        for (int k = 0; k < 8; ++k) {
            int c  = c0 + k;
            int gc = cb + c;
            int xlo = gc - RAD; if (xlo < 0) xlo = 0;
            int xhi = gc + RAD; if (xhi > LW - 1) xhi = LW - 1;
            float invN = 1.0f / ((float)(xhi - xlo + 1) * ny);

            float mx  = sx  * invN;
            float my  = sy  * invN;
            float cov = sxy * invN - mx * my;
            float var = sxx * invN - mx * mx;
            float A   = cov / (var + 1e-8f);
            g_AB[abase + gc] = make_float2(A, my - A * mx);

            if (k < 7) {
                float4 a = Vsh[i][vpad(c + 2 * RAD + 1)];
                float4 s = Vsh[i][vpad(c)];
                sx += a.x - s.x; sy += a.y - s.y;
                sxy += a.z - s.z; sxx += a.w - s.w;
            }
        }
    }
}

// ---------------------------------------------------------------------------
// Kernel 2: fused bilinear upsample. Extends the validated R15 MLP fix:
// 2 output rows per block, ALL FOUR hr_x float4 loads hoisted to the top
// (512B/thread-warp-slot in flight through setup). smem 8.2 KB; launch
// bounds force >=6 blocks/SM so occupancy stays high.
// ---------------------------------------------------------------------------
#define UPTHREADS 256
#define UROWS 2

__global__ __launch_bounds__(UPTHREADS, 6) void upsample_kernel(
        const float* __restrict__ hrx, float* __restrict__ out) {
    int bid = blockIdx.x;
    int img = bid >> 10;                  // 1024 row-pairs per image
    int oyb = (bid & 1023) * UROWS;
    int t   = threadIdx.x;

    const float SC = 511.0f / 2047.0f;

    // ---- issue all four streaming reads FIRST (independent of shared) ----
    size_t row0 = ((size_t)img * HW + oyb) * HW;
    size_t row1 = row0 + HW;
    int xq0 = t * 4;
    int xq1 = 1024 + t * 4;
    float4 h00 = __ldcs(reinterpret_cast<const float4*>(hrx + row0 + xq0));
    float4 h01 = __ldcs(reinterpret_cast<const float4*>(hrx + row0 + xq1));
    float4 h10 = __ldcs(reinterpret_cast<const float4*>(hrx + row1 + xq0));
    float4 h11 = __ldcs(reinterpret_cast<const float4*>(hrx + row1 + xq1));

    __shared__ float2 sAB[UROWS][LW + 1];   // y-interp {A,b}; col 512 = dup

#pragma unroll
    for (int rr = 0; rr < UROWS; ++rr) {
        int oy = oyb + rr;
        float yf = (float)oy * SC;
        int y0 = (int)yf; if (y0 > LH - 1) y0 = LH - 1;
        int y1 = y0 + 1;  if (y1 > LH - 1) y1 = LH - 1;
        float wy = yf - (float)y0;

        const float2* AB0 = g_AB + ((size_t)img * LH + y0) * LW;
        const float2* AB1 = g_AB + ((size_t)img * LH + y1) * LW;
#pragma unroll
        for (int i = 0; i < 2; ++i) {
            int xc = t + i * UPTHREADS;
            float2 v0 = AB0[xc];
            float2 v1 = AB1[xc];
            sAB[rr][xc] = make_float2(v0.x + wy * (v1.x - v0.x),
                                      v0.y + wy * (v1.y - v0.y));
        }
        if (t == 0) {
            float2 v0 = AB0[LW - 1];
            float2 v1 = AB1[LW - 1];
            sAB[rr][LW] = make_float2(v0.x + wy * (v1.x - v0.x),
                                      v0.y + wy * (v1.y - v0.y));
        }
    }
    __syncthreads();

#pragma unroll
    for (int c4 = 0; c4 < 4; ++c4) {
        int rr   = c4 >> 1;                 // row in pair
        int half = c4 & 1;
        int xq   = half ? xq1 : xq0;
        float4 hr = (c4 == 0) ? h00 : (c4 == 1) ? h01 : (c4 == 2) ? h10 : h11;
        float hv[4] = {hr.x, hr.y, hr.z, hr.w};

        float f0 = (float)xq * SC;
        int xb = (int)f0;                   // <= 510 (xq <= 2044)
        float fb = (float)xb;
        float2 p0 = sAB[rr][xb];
        float2 p1 = sAB[rr][xb + 1];
        float2 p2 = sAB[rr][xb + 2];        // <= 512: padded entry

        float res[4];
#pragma unroll
        for (int k = 0; k < 4; ++k) {
            float f = (float)(xq + k) * SC;
            bool c = (f - fb) >= 1.0f;      // x0 == xb+1 ?
            float wx = f - (c ? fb + 1.0f : fb);
            float pA = c ? p1.x : p0.x;
            float pB = c ? p1.y : p0.y;
            float qA = c ? p2.x : p1.x;
            float qB = c ? p2.y : p1.y;
            float Av = pA + wx * (qA - pA);
            float Bv = pB + wx * (qB - pB);
            res[k] = Av * hv[k] + Bv;
        }

        size_t off = (rr ? row1 : row0) + xq;
        __stcs(reinterpret_cast<float4*>(out + off),
               make_float4(res[0], res[1], res[2], res[3]));
    }
}

// ---------------------------------------------------------------------------
extern "C" void kernel_launch(void* const* d_in, const int* in_sizes, int n_in,
                              void* d_out, int out_size) {
    const float* lrx = (const float*)d_in[0];
    const float* lry = (const float*)d_in[1];
    const float* hrx = (const float*)d_in[2];
    float* out = (float*)d_out;

    dim3 sgrid(LW / TC, LH / TR, NIMG);      // 8 x 32 x 12 = 3072 blocks
    stats_kernel<<<sgrid, STH>>>(lrx, lry);

    upsample_kernel<<<NIMG * (HW / UROWS), UPTHREADS>>>(hrx, out);
}